// round 8
// baseline (speedup 1.0000x reference)
#include <cuda_runtime.h>
#include <cuda_bf16.h>
#include <cstdint>

#define NROWS 16384
#define BDIM  8192
#define DDIM  128
#define THREADS 256
#define SM_A   0
#define SM_B0  32768
#define SM_B1  65536
#define SM_TOTAL 98304         // 96 KB -> 2 CTAs/SM (192 KB of 228 KB)

// allocation-free scratch
__device__ float  g_denom[NROWS];
__device__ float  g_sppos[NROWS];
__device__ double g_total;
__device__ unsigned int g_count;
__device__ __nv_bfloat16 g_z[NROWS * DDIM];   // 4 MB, L2-resident

// ---------------- helpers ----------------
__device__ __forceinline__ uint32_t smem_u32(const void* p) {
    uint32_t a;
    asm("{ .reg .u64 t; cvta.to.shared.u64 t, %1; cvt.u32.u64 %0, t; }" : "=r"(a) : "l"(p));
    return a;
}
#define LDSM4(r, addr) \
    asm volatile("ldmatrix.sync.aligned.m8n8.x4.shared.b16 {%0,%1,%2,%3}, [%4];" \
        : "=r"((r)[0]), "=r"((r)[1]), "=r"((r)[2]), "=r"((r)[3]) : "r"(addr))
#define MMA16816(d, a, b0, b1) \
    asm volatile("mma.sync.aligned.m16n8k16.row.col.f32.bf16.bf16.f32 " \
        "{%0,%1,%2,%3}, {%4,%5,%6,%7}, {%8,%9}, {%0,%1,%2,%3};" \
        : "+f"((d)[0]), "+f"((d)[1]), "+f"((d)[2]), "+f"((d)[3]) \
        : "r"((a)[0]), "r"((a)[1]), "r"((a)[2]), "r"((a)[3]), "r"(b0), "r"(b1))

// 128x128 bf16 tile: smem row = 256B, 16B chunk c stored at c ^ (row & 7)
__device__ __forceinline__ void load_tile_async(uint32_t sdst, const __nv_bfloat16* gsrc, int tid) {
    #pragma unroll
    for (int it = 0; it < 8; it++) {
        int i = tid + it * THREADS;          // 0..2047
        int row = i >> 4, c = i & 15;
        uint32_t dst = sdst + (uint32_t)(row * 256 + ((c ^ (row & 7)) * 16));
        const void* src = gsrc + (size_t)row * DDIM + c * 8;
        asm volatile("cp.async.cg.shared.global [%0], [%1], 16;" :: "r"(dst), "l"(src));
    }
}
#define CP_COMMIT() asm volatile("cp.async.commit_group;" ::: "memory")
#define CP_WAIT0()  asm volatile("cp.async.wait_group 0;" ::: "memory")

// ---------------- convert + init (merged) ----------------
__global__ void convert_kernel(const float* __restrict__ za, const float* __restrict__ zb) {
    int i4 = blockIdx.x * blockDim.x + threadIdx.x;
    if (i4 < NROWS) g_denom[i4] = 0.0f;
    if (i4 == 0) { g_total = 0.0; g_count = 0u; }
    if (i4 >= NROWS * DDIM / 4) return;
    float4 v = (i4 < BDIM * DDIM / 4) ? ((const float4*)za)[i4]
                                      : ((const float4*)zb)[i4 - BDIM * DDIM / 4];
    ((__nv_bfloat162*)g_z)[i4 * 2]     = __nv_bfloat162(__float2bfloat16(v.x), __float2bfloat16(v.y));
    ((__nv_bfloat162*)g_z)[i4 * 2 + 1] = __nv_bfloat162(__float2bfloat16(v.z), __float2bfloat16(v.w));
}

// ---------------- fused strip kernel ----------------
__device__ __forceinline__ void map_tile(int p, int qq, int& bi, int& bj) {
    bi = p; bj = p + qq;
    if (bj >= 128) { bi = 127 - p; bj = qq - 1; }
}

__device__ __forceinline__ void flush_rsum(float (&rsum)[2][2], int bi, int warp_m, int lane) {
    #pragma unroll
    for (int mt = 0; mt < 2; mt++)
        #pragma unroll
        for (int h = 0; h < 2; h++) {
            float v = rsum[mt][h];
            v += __shfl_xor_sync(0xffffffffu, v, 1);
            v += __shfl_xor_sync(0xffffffffu, v, 2);
            if ((lane & 3) == 0)
                atomicAdd(&g_denom[bi * 128 + warp_m * 32 + mt * 16 + (lane >> 2) + h * 8], v);
            rsum[mt][h] = 0.0f;
        }
}

__global__ __launch_bounds__(THREADS, 2)
void fused_strip_kernel() {
    extern __shared__ char smem[];
    const uint32_t sbase = smem_u32(smem);
    const int tid    = threadIdx.x;
    const int lane   = tid & 31;
    const int wid    = tid >> 5;
    const int warp_m = wid & 3;            // 4 row blocks of 32
    const int warp_n = wid >> 2;           // 2 col blocks of 64
    const int p = blockIdx.y;              // 0..63
    const int q = blockIdx.x;              // 0..42, strip of 3 folded columns

    const int a_row = warp_m * 32 + (lane & 7) + ((lane >> 3) & 1) * 8;
    const int a_kc  = lane >> 4;
    const int b_row = warp_n * 64 + (lane & 7) + ((lane >> 4) & 1) * 8;
    const int b_kc  = (lane >> 3) & 1;

    int bi0, bj0;
    map_tile(p, q * 3, bi0, bj0);
    load_tile_async(sbase + SM_A,  g_z + (size_t)bi0 * 128 * DDIM, tid);
    load_tile_async(sbase + SM_B0, g_z + (size_t)bj0 * 128 * DDIM, tid);
    CP_COMMIT();

    int cur_bi = bi0;
    float rsum[2][2] = {{0.f, 0.f}, {0.f, 0.f}};

    #pragma unroll
    for (int t = 0; t < 3; t++) {
        int bi, bj;
        map_tile(p, q * 3 + t, bi, bj);

        CP_WAIT0();
        __syncthreads();

        if (bi != cur_bi) {                 // fold crossing: rare (64 strips total)
            flush_rsum(rsum, cur_bi, warp_m, lane);
            cur_bi = bi;
            load_tile_async(sbase + SM_A, g_z + (size_t)bi * 128 * DDIM, tid);
            CP_COMMIT(); CP_WAIT0();
            __syncthreads();
        }

        const uint32_t bbase = sbase + SM_B0 + (uint32_t)(t & 1) * 32768u;

        float acc[2][8][4];
        #pragma unroll
        for (int mt = 0; mt < 2; mt++)
            #pragma unroll
            for (int nl = 0; nl < 8; nl++)
                #pragma unroll
                for (int i = 0; i < 4; i++) acc[mt][nl][i] = 0.f;

        #pragma unroll
        for (int ks = 0; ks < 8; ks++) {
            uint32_t a[2][4], b[4][4];
            #pragma unroll
            for (int mt = 0; mt < 2; mt++) {
                int row = a_row + mt * 16;
                int ch  = (ks * 2 + a_kc) ^ (row & 7);
                LDSM4(a[mt], sbase + SM_A + (uint32_t)(row * 256 + ch * 16));
            }
            #pragma unroll
            for (int g = 0; g < 4; g++) {
                int row = b_row + g * 16;
                int ch  = (ks * 2 + b_kc) ^ (row & 7);
                LDSM4(b[g], bbase + (uint32_t)(row * 256 + ch * 16));
            }
            #pragma unroll
            for (int mt = 0; mt < 2; mt++)
                #pragma unroll
                for (int nl = 0; nl < 8; nl++)
                    MMA16816(acc[mt][nl], a[mt], b[nl >> 1][(nl & 1) * 2], b[nl >> 1][(nl & 1) * 2 + 1]);
        }
        __syncthreads();                    // all warps done reading smem B buf

        // prefetch next B during the epilogue (hides the whole global load)
        if (t < 2) {
            int nbi, nbj;
            map_tile(p, q * 3 + t + 1, nbi, nbj);
            load_tile_async(sbase + SM_B0 + (uint32_t)((t + 1) & 1) * 32768u,
                            g_z + (size_t)nbj * 128 * DDIM, tid);
            CP_COMMIT();
        }

        // ---- fused epilogue (registers + atomics only) ----
        const bool diag = (bi == bj);
        const bool pos  = (bj == (bi ^ 64));
        const bool dp   = diag || pos;
        float csum[16];
        #pragma unroll
        for (int c = 0; c < 16; c++) csum[c] = 0.f;

        #pragma unroll
        for (int mt = 0; mt < 2; mt++)
            #pragma unroll
            for (int nl = 0; nl < 8; nl++)
                #pragma unroll
                for (int i = 0; i < 4; i++) {
                    float v = acc[mt][nl][i];
                    float x = v + v;                              // sim / tau
                    float e;
                    asm("ex2.approx.ftz.f32 %0, %1;" : "=f"(e) : "f"(v * 2.8853900817779268f));
                    float l;
                    asm("lg2.approx.ftz.f32 %0, %1;" : "=f"(l) : "f"(1.0f + e));
                    float sp  = 0.6931471805599453f * l;
                    float spn = __fmaf_rn(-0.5f * e, e, e);       // x << 0
                    sp = (x < -9.0f) ? spn : sp;
                    sp = (x > 15.0f) ? x : sp;
                    if (dp) {                                     // uniform, rare branch
                        const int lr = warp_m * 32 + mt * 16 + (lane >> 2) + (i >> 1) * 8;
                        const int lc = warp_n * 64 + nl * 8 + (lane & 3) * 2 + (i & 1);
                        if (lr == lc) {
                            if (diag) sp = 0.0f;
                            else {
                                g_sppos[bi * 128 + lr] = sp;
                                g_sppos[bj * 128 + lc] = sp;
                            }
                        }
                    }
                    rsum[mt][i >> 1] += sp;
                    csum[nl * 2 + (i & 1)] += sp;
                }

        // col sums -> g_denom (skip for diag: symmetric self-tile already counted by rows)
        if (!diag) {
            #pragma unroll
            for (int c = 0; c < 16; c++) {
                float v = csum[c];
                v += __shfl_xor_sync(0xffffffffu, v, 4);
                v += __shfl_xor_sync(0xffffffffu, v, 8);
                v += __shfl_xor_sync(0xffffffffu, v, 16);
                if (lane < 4)
                    atomicAdd(&g_denom[bj * 128 + warp_n * 64 + (c >> 1) * 8 + lane * 2 + (c & 1)], v);
            }
        }
    }

    flush_rsum(rsum, cur_bi, warp_m, lane);
}

// ---------------- parallel finalize (last block writes out) ----------------
__global__ void finalize_part(float* __restrict__ out) {
    __shared__ double red[256];
    const int i = blockIdx.x * 256 + threadIdx.x;     // 64*256 == NROWS exactly
    float spp = fmaxf(g_sppos[i], 1e-8f);
    float den = fmaxf(g_denom[i], 1e-8f);
    red[threadIdx.x] = (double)(logf(spp) - logf(den));
    __syncthreads();
    for (int o = 128; o > 0; o >>= 1) {
        if (threadIdx.x < o) red[threadIdx.x] += red[threadIdx.x + o];
        __syncthreads();
    }
    if (threadIdx.x == 0) {
        atomicAdd(&g_total, red[0]);
        __threadfence();
        unsigned int done = atomicAdd(&g_count, 1u);
        if (done == 63u) {
            __threadfence();
            double tot = *((volatile double*)&g_total);
            out[0] = (float)(-tot / (double)NROWS);
        }
    }
}

extern "C" void kernel_launch(void* const* d_in, const int* in_sizes, int n_in,
                              void* d_out, int out_size) {
    const float* za = (const float*)d_in[0];
    const float* zb = (const float*)d_in[1];
    float* out = (float*)d_out;

    cudaFuncSetAttribute(fused_strip_kernel, cudaFuncAttributeMaxDynamicSharedMemorySize, SM_TOTAL);

    convert_kernel<<<(NROWS * DDIM / 4 + 255) / 256, 256>>>(za, zb);
    dim3 grid(43, 64);                    // 43 strips of 3 = 129 folded cols, exact cover
    fused_strip_kernel<<<grid, THREADS, SM_TOTAL>>>();
    finalize_part<<<64, 256>>>(out);
}

// round 10
// speedup vs baseline: 1.0787x; 1.0787x over previous
#include <cuda_runtime.h>
#include <cuda_bf16.h>
#include <cstdint>

#define NROWS 16384
#define BDIM  8192
#define DDIM  128
#define THREADS 256
#define SM_A    0
#define SM_B0   32768
#define SM_B1   65536
#define SM_RED  98304
#define SM_TOTAL (98304 + 3072)   // A + B0 + B1 + reduction scratch = 99 KB -> 2 CTAs/SM

// allocation-free scratch
__device__ float  g_denom[NROWS];
__device__ float  g_sppos[NROWS];
__device__ double g_total;
__device__ unsigned int g_count;
__device__ __nv_bfloat16 g_z[NROWS * DDIM];   // 4 MB, L2-resident

// ---------------- helpers ----------------
__device__ __forceinline__ uint32_t smem_u32(const void* p) {
    uint32_t a;
    asm("{ .reg .u64 t; cvta.to.shared.u64 t, %1; cvt.u32.u64 %0, t; }" : "=r"(a) : "l"(p));
    return a;
}
#define LDSM4(r, addr) \
    asm volatile("ldmatrix.sync.aligned.m8n8.x4.shared.b16 {%0,%1,%2,%3}, [%4];" \
        : "=r"((r)[0]), "=r"((r)[1]), "=r"((r)[2]), "=r"((r)[3]) : "r"(addr))
#define MMA16816(d, a, b0, b1) \
    asm volatile("mma.sync.aligned.m16n8k16.row.col.f32.bf16.bf16.f32 " \
        "{%0,%1,%2,%3}, {%4,%5,%6,%7}, {%8,%9}, {%0,%1,%2,%3};" \
        : "+f"((d)[0]), "+f"((d)[1]), "+f"((d)[2]), "+f"((d)[3]) \
        : "r"((a)[0]), "r"((a)[1]), "r"((a)[2]), "r"((a)[3]), "r"(b0), "r"(b1))

// 128x128 bf16 tile: smem row = 256B, 16B chunk c stored at c ^ (row & 7)
__device__ __forceinline__ void load_tile_async(uint32_t sdst, const __nv_bfloat16* gsrc, int tid) {
    #pragma unroll
    for (int it = 0; it < 8; it++) {
        int i = tid + it * THREADS;          // 0..2047
        int row = i >> 4, c = i & 15;
        uint32_t dst = sdst + (uint32_t)(row * 256 + ((c ^ (row & 7)) * 16));
        const void* src = gsrc + (size_t)row * DDIM + c * 8;
        asm volatile("cp.async.cg.shared.global [%0], [%1], 16;" :: "r"(dst), "l"(src));
    }
}
#define CP_COMMIT() asm volatile("cp.async.commit_group;" ::: "memory")
#define CP_WAIT0()  asm volatile("cp.async.wait_group 0;" ::: "memory")

// ---------------- convert + init (merged) ----------------
__global__ void convert_kernel(const float* __restrict__ za, const float* __restrict__ zb) {
    int i4 = blockIdx.x * blockDim.x + threadIdx.x;
    if (i4 < NROWS) g_denom[i4] = 0.0f;
    if (i4 == 0) { g_total = 0.0; g_count = 0u; }
    if (i4 >= NROWS * DDIM / 4) return;
    float4 v = (i4 < BDIM * DDIM / 4) ? ((const float4*)za)[i4]
                                      : ((const float4*)zb)[i4 - BDIM * DDIM / 4];
    ((__nv_bfloat162*)g_z)[i4 * 2]     = __nv_bfloat162(__float2bfloat16(v.x), __float2bfloat16(v.y));
    ((__nv_bfloat162*)g_z)[i4 * 2 + 1] = __nv_bfloat162(__float2bfloat16(v.z), __float2bfloat16(v.w));
}

// exact rectangle -> upper-triangle fold
__device__ __forceinline__ void map_tile(int p, int qq, int& bi, int& bj) {
    bi = p; bj = p + qq;
    if (bj >= 128) { bi = 127 - p; bj = qq - 1; }
}

// ---------------- fused 2-tile-strip kernel ----------------
__global__ __launch_bounds__(THREADS, 2)
void fused_strip_kernel() {
    extern __shared__ char smem[];
    const uint32_t sbase = smem_u32(smem);
    const int tid    = threadIdx.x;
    const int lane   = tid & 31;
    const int wid    = tid >> 5;
    const int warp_m = wid & 3;            // 4 row blocks of 32
    const int warp_n = wid >> 2;           // 2 col blocks of 64
    const int p = blockIdx.y;              // 0..63
    const int q = blockIdx.x;              // 0..64 -> tiles {2q, 2q+1} (q=64: only 128)

    const int a_row = warp_m * 32 + (lane & 7) + ((lane >> 3) & 1) * 8;
    const int a_kc  = lane >> 4;
    const int b_row = warp_n * 64 + (lane & 7) + ((lane >> 4) & 1) * 8;
    const int b_kc  = (lane >> 3) & 1;

    const int ntiles = (q == 64) ? 1 : 2;
    int bi0, bj0;
    map_tile(p, q * 2, bi0, bj0);
    load_tile_async(sbase + SM_A,  g_z + (size_t)bi0 * 128 * DDIM, tid);
    load_tile_async(sbase + SM_B0, g_z + (size_t)bj0 * 128 * DDIM, tid);
    CP_COMMIT();
    int cur_bi = bi0;

    for (int t = 0; t < ntiles; t++) {
        int bi, bj;
        map_tile(p, q * 2 + t, bi, bj);

        CP_WAIT0();
        __syncthreads();

        if (bi != cur_bi) {                // fold crossing inside strip: rare (<=64 CTAs)
            cur_bi = bi;
            load_tile_async(sbase + SM_A, g_z + (size_t)bi * 128 * DDIM, tid);
            CP_COMMIT(); CP_WAIT0();
            __syncthreads();
        }

        const uint32_t bbase = sbase + SM_B0 + (uint32_t)(t & 1) * 32768u;

        float acc[2][8][4];
        #pragma unroll
        for (int mt = 0; mt < 2; mt++)
            #pragma unroll
            for (int nl = 0; nl < 8; nl++)
                #pragma unroll
                for (int i = 0; i < 4; i++) acc[mt][nl][i] = 0.f;

        #pragma unroll
        for (int ks = 0; ks < 8; ks++) {
            uint32_t a[2][4], b[4][4];
            #pragma unroll
            for (int mt = 0; mt < 2; mt++) {
                int row = a_row + mt * 16;
                int ch  = (ks * 2 + a_kc) ^ (row & 7);
                LDSM4(a[mt], sbase + SM_A + (uint32_t)(row * 256 + ch * 16));
            }
            #pragma unroll
            for (int g = 0; g < 4; g++) {
                int row = b_row + g * 16;
                int ch  = (ks * 2 + b_kc) ^ (row & 7);
                LDSM4(b[g], bbase + (uint32_t)(row * 256 + ch * 16));
            }
            #pragma unroll
            for (int mt = 0; mt < 2; mt++)
                #pragma unroll
                for (int nl = 0; nl < 8; nl++)
                    MMA16816(acc[mt][nl], a[mt], b[nl >> 1][(nl & 1) * 2], b[nl >> 1][(nl & 1) * 2 + 1]);
        }

        // prefetch next B into the other buffer: flies under the MUFU epilogue.
        // Safe: next buffer's previous readers (tile t-1 MMA) finished before the
        // __syncthreads at the top of this iteration.
        if (t + 1 < ntiles) {
            int nbi, nbj;
            map_tile(p, q * 2 + t + 1, nbi, nbj);
            load_tile_async(sbase + SM_B0 + (uint32_t)((t + 1) & 1) * 32768u,
                            g_z + (size_t)nbj * 128 * DDIM, tid);
            CP_COMMIT();
        }

        // ---- fused epilogue (identical math to R6) ----
        const bool diag = (bi == bj);
        const bool pos  = (bj == (bi ^ 64));
        const bool dp   = diag || pos;
        float rsum[2][2] = {{0.f, 0.f}, {0.f, 0.f}};
        float csum[16];
        #pragma unroll
        for (int c = 0; c < 16; c++) csum[c] = 0.f;

        #pragma unroll
        for (int mt = 0; mt < 2; mt++)
            #pragma unroll
            for (int nl = 0; nl < 8; nl++)
                #pragma unroll
                for (int i = 0; i < 4; i++) {
                    float v = acc[mt][nl][i];
                    float x = v + v;                              // sim / tau, tau = 0.5
                    float e;
                    asm("ex2.approx.ftz.f32 %0, %1;" : "=f"(e) : "f"(v * 2.8853900817779268f));
                    float l;
                    asm("lg2.approx.ftz.f32 %0, %1;" : "=f"(l) : "f"(1.0f + e));
                    float sp  = 0.6931471805599453f * l;
                    float spn = __fmaf_rn(-0.5f * e, e, e);       // x << 0: e^x - e^2x/2
                    sp = (x < -9.0f) ? spn : sp;
                    sp = (x > 15.0f) ? x : sp;
                    if (dp) {
                        const int lr = warp_m * 32 + mt * 16 + (lane >> 2) + (i >> 1) * 8;
                        const int lc = warp_n * 64 + nl * 8 + (lane & 3) * 2 + (i & 1);
                        if (lr == lc) {
                            if (diag) sp = 0.0f;
                            else {
                                g_sppos[bi * 128 + lr] = sp;
                                g_sppos[bj * 128 + lc] = sp;
                            }
                        }
                    }
                    rsum[mt][i >> 1] += sp;
                    csum[nl * 2 + (i & 1)] += sp;
                }

        // ---- reductions via dedicated smem (A/B stay live), R6-style ----
        float* srow = (float*)(smem + SM_RED);          // [2][128]
        float* scol = (float*)(smem + SM_RED + 1024);   // [4][128]
        #pragma unroll
        for (int mt = 0; mt < 2; mt++)
            #pragma unroll
            for (int h = 0; h < 2; h++) {
                float v = rsum[mt][h];
                v += __shfl_xor_sync(0xffffffffu, v, 1);
                v += __shfl_xor_sync(0xffffffffu, v, 2);
                if ((lane & 3) == 0)
                    srow[warp_n * 128 + warp_m * 32 + mt * 16 + (lane >> 2) + h * 8] = v;
            }
        if (!diag) {
            #pragma unroll
            for (int c = 0; c < 16; c++) {
                float v = csum[c];
                v += __shfl_xor_sync(0xffffffffu, v, 4);
                v += __shfl_xor_sync(0xffffffffu, v, 8);
                v += __shfl_xor_sync(0xffffffffu, v, 16);
                if (lane < 4)
                    scol[warp_m * 128 + warp_n * 64 + (c >> 1) * 8 + lane * 2 + (c & 1)] = v;
            }
        }
        __syncthreads();
        if (tid < 128) {
            float rt = srow[tid] + srow[128 + tid];
            atomicAdd(&g_denom[bi * 128 + tid], rt);
            if (!diag) {
                float ct = scol[tid] + scol[128 + tid] + scol[256 + tid] + scol[384 + tid];
                atomicAdd(&g_denom[bj * 128 + tid], ct);
            }
        }
        // next iteration's top __syncthreads fences srow/scol reuse
    }
}

// ---------------- parallel finalize (last block writes out) ----------------
__global__ void finalize_part(float* __restrict__ out) {
    __shared__ double red[256];
    const int i = blockIdx.x * 256 + threadIdx.x;     // 64*256 == NROWS exactly
    float spp = fmaxf(g_sppos[i], 1e-8f);
    float den = fmaxf(g_denom[i], 1e-8f);
    red[threadIdx.x] = (double)(logf(spp) - logf(den));
    __syncthreads();
    for (int o = 128; o > 0; o >>= 1) {
        if (threadIdx.x < o) red[threadIdx.x] += red[threadIdx.x + o];
        __syncthreads();
    }
    if (threadIdx.x == 0) {
        atomicAdd(&g_total, red[0]);
        __threadfence();
        unsigned int done = atomicAdd(&g_count, 1u);
        if (done == 63u) {
            __threadfence();
            double tot = *((volatile double*)&g_total);
            out[0] = (float)(-tot / (double)NROWS);
        }
    }
}

extern "C" void kernel_launch(void* const* d_in, const int* in_sizes, int n_in,
                              void* d_out, int out_size) {
    const float* za = (const float*)d_in[0];
    const float* zb = (const float*)d_in[1];
    float* out = (float*)d_out;

    cudaFuncSetAttribute(fused_strip_kernel, cudaFuncAttributeMaxDynamicSharedMemorySize, SM_TOTAL);

    convert_kernel<<<(NROWS * DDIM / 4 + 255) / 256, 256>>>(za, zb);
    dim3 grid(65, 64);                    // 65 strips of <=2 tiles = 129 folded cols, exact cover
    fused_strip_kernel<<<grid, THREADS, SM_TOTAL>>>();
    finalize_part<<<64, 256>>>(out);
}